// round 15
// baseline (speedup 1.0000x reference)
#include <cuda_runtime.h>
#include <cuda_bf16.h>
#include <cstdint>

#define N_NODES 100000
#define N_EDGES 1600000
#define N_GRAPHS 512
#define FDIM 128
#define SCAN_CHUNK 512
#define SCAN_BLOCKS ((N_NODES + SCAN_CHUNK - 1) / SCAN_CHUNK)   // 196
#define SMS 24
#define WS2 136
#define SMEM_G ((3072 * 2 + 17408 * 2) * 2)   // 81920 B
#define NCHUNK 4

static const int CH[NCHUNK + 1] = {0, 25088, 50176, 75264, 100000};  // 128-aligned

// ---------------- device scratch (allocation-free: __device__ globals) ------
__device__ float    g_hA[(size_t)N_NODES * FDIM];
__device__ float    g_agg[(size_t)N_NODES * FDIM];
__device__ __align__(16) __nv_bfloat16 g_ah[(size_t)N_NODES * FDIM];
__device__ __align__(16) __nv_bfloat16 g_al[(size_t)N_NODES * FDIM];
__device__ __align__(16) __nv_bfloat16 g_wth[3][FDIM * FDIM];
__device__ __align__(16) __nv_bfloat16 g_wtl[3][FDIM * FDIM];
__device__ int      g_deg[N_NODES];
__device__ int      g_cursor[N_NODES];
__device__ float    g_dinv[N_NODES];
__device__ int      g_rowoff[N_NODES + 1];
__device__ unsigned long long g_edge[N_EDGES];
__device__ int      g_part[SCAN_BLOCKS];
__device__ float    g_sums[N_GRAPHS * FDIM];
__device__ unsigned g_maxenc[N_GRAPHS * FDIM];
__device__ int      g_cnt[N_GRAPHS];

// ---------------- helpers ---------------------------------------------------
__device__ __forceinline__ unsigned enc_max(float f) {
    unsigned u = __float_as_uint(f);
    return (u & 0x80000000u) ? ~u : (u | 0x80000000u);
}
__device__ __forceinline__ float dec_max(unsigned e) {
    unsigned bits = (e & 0x80000000u) ? (e ^ 0x80000000u) : ~e;
    return __uint_as_float(bits);
}
__device__ __forceinline__ void mma_bf16(float* c, const uint32_t* a,
                                         uint32_t b0, uint32_t b1) {
    asm volatile(
        "mma.sync.aligned.m16n8k16.row.col.f32.bf16.bf16.f32 "
        "{%0,%1,%2,%3}, {%4,%5,%6,%7}, {%8,%9}, {%0,%1,%2,%3};"
        : "+f"(c[0]), "+f"(c[1]), "+f"(c[2]), "+f"(c[3])
        : "r"(a[0]), "r"(a[1]), "r"(a[2]), "r"(a[3]), "r"(b0), "r"(b1));
}
__device__ __forceinline__ uint32_t pack_hi2(float v0, float v1, float& h0f, float& h1f) {
    __nv_bfloat16 h0 = __float2bfloat16(v0), h1 = __float2bfloat16(v1);
    h0f = __bfloat162float(h0); h1f = __bfloat162float(h1);
    __nv_bfloat162 p; p.x = h0; p.y = h1;
    return *(uint32_t*)&p;
}
__device__ __forceinline__ uint32_t pack_bf2(float v0, float v1) {
    __nv_bfloat162 p; p.x = __float2bfloat16(v0); p.y = __float2bfloat16(v1);
    return *(uint32_t*)&p;
}

// ---------------- preprocessing ---------------------------------------------
__global__ void zero_kernel() {
    int i = blockIdx.x * blockDim.x + threadIdx.x;
    if (i < N_GRAPHS * FDIM) { g_sums[i] = 0.0f; g_maxenc[i] = 0u; }
    if (i < N_GRAPHS) g_cnt[i] = 0;
    if (i < N_NODES) g_deg[i] = 0;
}

__global__ void hist_kernel(const int* __restrict__ dst) {
    int stride = gridDim.x * blockDim.x;
    for (int e = blockIdx.x * blockDim.x + threadIdx.x; e < N_EDGES; e += stride)
        atomicAdd(&g_deg[dst[e]], 1);
}

__global__ void scan_part() {
    int b = blockIdx.x, t = threadIdx.x;
    int base = b * SCAN_CHUNK;
    int s = 0;
    for (int i = t; i < SCAN_CHUNK; i += 256) {
        int idx = base + i;
        if (idx < N_NODES) s += g_deg[idx];
    }
    __shared__ int sh[8];
#pragma unroll
    for (int o = 16; o; o >>= 1) s += __shfl_down_sync(~0u, s, o);
    if ((t & 31) == 0) sh[t >> 5] = s;
    __syncthreads();
    if (t < 8) {
        int v = sh[t];
#pragma unroll
        for (int o = 4; o; o >>= 1) v += __shfl_down_sync(0xffu, v, o);
        if (t == 0) g_part[b] = v;
    }
}

__global__ void scan_mid() {
    __shared__ int sh[256];
    int t = threadIdx.x;
    int v = (t < SCAN_BLOCKS) ? g_part[t] : 0;
    sh[t] = v;
    __syncthreads();
    for (int o = 1; o < 256; o <<= 1) {
        int u = (t >= o) ? sh[t - o] : 0;
        __syncthreads();
        sh[t] += u;
        __syncthreads();
    }
    if (t < SCAN_BLOCKS) g_part[t] = sh[t] - v;
    if (t == 0) g_rowoff[N_NODES] = N_EDGES;
}

__global__ void scan_final() {
    int b = blockIdx.x, t = threadIdx.x;
    int base = b * SCAN_CHUNK;
    int i0 = base + 2 * t, i1 = i0 + 1;
    int d0 = (i0 < N_NODES) ? g_deg[i0] : 0;
    int d1 = (i1 < N_NODES) ? g_deg[i1] : 0;
    int s = d0 + d1;
    __shared__ int sh[256];
    sh[t] = s;
    __syncthreads();
    for (int o = 1; o < 256; o <<= 1) {
        int u = (t >= o) ? sh[t - o] : 0;
        __syncthreads();
        sh[t] += u;
        __syncthreads();
    }
    int excl = sh[t] - s + g_part[b];
    if (i0 < N_NODES) {
        g_rowoff[i0] = excl;
        g_dinv[i0] = rsqrtf((float)d0 + 1.0f);
        g_cursor[i0] = 0;
    }
    if (i1 < N_NODES) {
        g_rowoff[i1] = excl + d0;
        g_dinv[i1] = rsqrtf((float)d1 + 1.0f);
        g_cursor[i1] = 0;
    }
}

__global__ void scatter_kernel(const int* __restrict__ src, const int* __restrict__ dst) {
    int stride = gridDim.x * blockDim.x;
    for (int e = blockIdx.x * blockDim.x + threadIdx.x; e < N_EDGES; e += stride) {
        int s = src[e], d = dst[e];
        int pos = g_rowoff[d] + atomicAdd(&g_cursor[d], 1);
        float norm = g_dinv[s] * g_dinv[d];
        g_edge[pos] = (unsigned long long)(unsigned)s |
                      ((unsigned long long)__float_as_uint(norm) << 32);
    }
}

// ---------------- weight split ----------------------------------------------
__global__ void split_w(const float* __restrict__ W1, const float* __restrict__ W2,
                        const float* __restrict__ W3) {
    int t = blockIdx.x * blockDim.x + threadIdx.x;
    if (t >= 3 * FDIM * FDIM) return;
    int l = t >> 14, i = t & 16383;
    int k = i >> 7, n = i & 127;
    const float* W = (l == 0) ? W1 : (l == 1) ? W2 : W3;
    float v = W[k * FDIM + n];
    __nv_bfloat16 h = __float2bfloat16(v);
    g_wth[l][n * FDIM + k] = h;
    g_wtl[l][n * FDIM + k] = __float2bfloat16(v - __bfloat162float(h));
}

__global__ void split_x(const float* __restrict__ x) {
    int i = blockIdx.x * blockDim.x + threadIdx.x;
    if (i >= N_NODES * FDIM / 4) return;
    float4 v = ((const float4*)x)[i];
    float h0, h1, h2, h3;
    uint32_t p01 = pack_hi2(v.x, v.y, h0, h1);
    uint32_t p23 = pack_hi2(v.z, v.w, h2, h3);
    *(uint2*)&g_ah[(size_t)i * 4] = make_uint2(p01, p23);
    *(uint2*)&g_al[(size_t)i * 4] =
        make_uint2(pack_bf2(v.x - h0, v.y - h1), pack_bf2(v.z - h2, v.w - h3));
}

// ---------------- HMMA GEMM (pre-split bf16): out = A @ W -------------------
__global__ void __launch_bounds__(256)
gemm_bf16(const __nv_bfloat16* __restrict__ Ah, const __nv_bfloat16* __restrict__ Al,
          const __nv_bfloat16* __restrict__ Wth, const __nv_bfloat16* __restrict__ Wtl,
          float* __restrict__ out, int row_base) {
    extern __shared__ __nv_bfloat16 sm[];
    __nv_bfloat16* Ahs = sm;
    __nv_bfloat16* Als = sm + 3072;
    __nv_bfloat16* Wsh = sm + 6144;
    __nv_bfloat16* Wsl = sm + 6144 + 17408;

    int tid = threadIdx.x, warp = tid >> 5, lane = tid & 31;
    int g = lane >> 2, q = lane & 3;
    int row0 = row_base + blockIdx.x * 128;

#pragma unroll
    for (int i = 0; i < 8; i++) {
        int idx = tid + i * 256;
        int n = idx >> 4, s = idx & 15;
        *(uint4*)&Wsh[n * WS2 + s * 8] = *(const uint4*)&Wth[n * FDIM + s * 8];
        *(uint4*)&Wsl[n * WS2 + s * 8] = *(const uint4*)&Wtl[n * FDIM + s * 8];
    }

    float acc[16][4];
#pragma unroll
    for (int nt = 0; nt < 16; nt++)
#pragma unroll
        for (int j = 0; j < 4; j++) acc[nt][j] = 0.0f;

    for (int ks = 0; ks < 8; ks++) {
        __syncthreads();
        {
            int r = tid >> 1, hf = tid & 1;
            int gr = row0 + r;
            if (gr >= N_NODES) gr = N_NODES - 1;
            size_t go = (size_t)gr * FDIM + ks * 16 + hf * 8;
            *(uint4*)&Ahs[r * SMS + hf * 8] = __ldcs((const uint4*)&Ah[go]);
            *(uint4*)&Als[r * SMS + hf * 8] = __ldcs((const uint4*)&Al[go]);
        }
        __syncthreads();

        int r0 = (warp * 16 + g) * SMS, r1 = r0 + 8 * SMS;
        uint32_t ah[4], al[4];
        ah[0] = *(const uint32_t*)&Ahs[r0 + q * 2];
        ah[1] = *(const uint32_t*)&Ahs[r1 + q * 2];
        ah[2] = *(const uint32_t*)&Ahs[r0 + q * 2 + 8];
        ah[3] = *(const uint32_t*)&Ahs[r1 + q * 2 + 8];
        al[0] = *(const uint32_t*)&Als[r0 + q * 2];
        al[1] = *(const uint32_t*)&Als[r1 + q * 2];
        al[2] = *(const uint32_t*)&Als[r0 + q * 2 + 8];
        al[3] = *(const uint32_t*)&Als[r1 + q * 2 + 8];

#pragma unroll
        for (int nt = 0; nt < 16; nt++) {
            int nb = (nt * 8 + g) * WS2 + ks * 16;
            uint32_t bh0 = *(const uint32_t*)&Wsh[nb + q * 2];
            uint32_t bh1 = *(const uint32_t*)&Wsh[nb + q * 2 + 8];
            uint32_t bl0 = *(const uint32_t*)&Wsl[nb + q * 2];
            uint32_t bl1 = *(const uint32_t*)&Wsl[nb + q * 2 + 8];
            mma_bf16(acc[nt], ah, bh0, bh1);
            mma_bf16(acc[nt], ah, bl0, bl1);
            mma_bf16(acc[nt], al, bh0, bh1);
        }
    }

    int rowa = row0 + warp * 16 + g;
    int rowb = rowa + 8;
#pragma unroll
    for (int nt = 0; nt < 16; nt++) {
        int col = nt * 8 + q * 2;
        if (rowa < N_NODES)
            *(float2*)(out + (size_t)rowa * FDIM + col) = make_float2(acc[nt][0], acc[nt][1]);
        if (rowb < N_NODES)
            *(float2*)(out + (size_t)rowb * FDIM + col) = make_float2(acc[nt][2], acc[nt][3]);
    }
}

// ---------------- aggregation core ------------------------------------------
__device__ __forceinline__ float4 agg_row(const float* __restrict__ h,
                                          const float* __restrict__ bias,
                                          int node, int lane) {
    float di = g_dinv[node];
    float sc = di * di;
    float4 b4 = ((const float4*)bias)[lane];
    float4 hv = ((const float4*)(h + (size_t)node * FDIM))[lane];
    float4 acc;
    acc.x = b4.x + hv.x * sc; acc.y = b4.y + hv.y * sc;
    acc.z = b4.z + hv.z * sc; acc.w = b4.w + hv.w * sc;

    int beg = g_rowoff[node];
    int deg = g_rowoff[node + 1] - beg;
    for (int base = 0; base < deg; base += 32) {
        int n = deg - base; if (n > 32) n = 32;
        unsigned lo = 0, hi = 0;
        if (base + lane < deg) {
            unsigned long long e = __ldg(&g_edge[beg + base + lane]);
            lo = (unsigned)e;
            hi = (unsigned)(e >> 32);
        }
#pragma unroll 4
        for (int j = 0; j < n; j++) {
            int s = (int)__shfl_sync(~0u, lo, j);
            float w = __uint_as_float(__shfl_sync(~0u, hi, j));
            float4 v = __ldg((const float4*)(h + (size_t)s * FDIM) + lane);
            acc.x += w * v.x; acc.y += w * v.y;
            acc.z += w * v.z; acc.w += w * v.w;
        }
    }
    return acc;
}

// conv-1/2 flavor: emit relu'd bf16 hi/lo for next GEMM (chunked)
__global__ void agg_split(const float* __restrict__ h, const float* __restrict__ bias,
                          int node0, int node1) {
    int warpid = (blockIdx.x * blockDim.x + threadIdx.x) >> 5;
    int lane = threadIdx.x & 31;
    int node = node0 + warpid;
    if (node >= node1) return;
    float4 a = agg_row(h, bias, node, lane);
    a.x = fmaxf(a.x, 0.f); a.y = fmaxf(a.y, 0.f);
    a.z = fmaxf(a.z, 0.f); a.w = fmaxf(a.w, 0.f);
    float h0, h1, h2, h3;
    uint32_t p01 = pack_hi2(a.x, a.y, h0, h1);
    uint32_t p23 = pack_hi2(a.z, a.w, h2, h3);
    size_t o = (size_t)node * FDIM + lane * 4;
    *(uint2*)&g_ah[o] = make_uint2(p01, p23);
    *(uint2*)&g_al[o] =
        make_uint2(pack_bf2(a.x - h0, a.y - h1), pack_bf2(a.z - h2, a.w - h3));
}

// conv-3 flavor: fp32 for pooling (chunked)
__global__ void agg_f32(const float* __restrict__ h, const float* __restrict__ bias,
                        float* __restrict__ out, int node0, int node1) {
    int warpid = (blockIdx.x * blockDim.x + threadIdx.x) >> 5;
    int lane = threadIdx.x & 31;
    int node = node0 + warpid;
    if (node >= node1) return;
    float4 a = agg_row(h, bias, node, lane);
    ((float4*)(out + (size_t)node * FDIM))[lane] = a;
}

// ---------------- pooling (chunked) -----------------------------------------
__global__ void pool_kernel(const int* __restrict__ batch, int node0, int node1) {
    int warpid = (blockIdx.x * blockDim.x + threadIdx.x) >> 5;
    int lane = threadIdx.x & 31;
    int beg = node0 + warpid * 32;
    if (beg >= node1) return;
    int end = min(beg + 32, node1);

    int cur = batch[beg];
    float4 s = make_float4(0.f, 0.f, 0.f, 0.f);
    float4 m = make_float4(-INFINITY, -INFINITY, -INFINITY, -INFINITY);
    int cnt = 0;

    for (int node = beg; node < end; node++) {
        int b = batch[node];
        if (b != cur) {
            int base = cur * FDIM + lane * 4;
            atomicAdd(&g_sums[base + 0], s.x); atomicAdd(&g_sums[base + 1], s.y);
            atomicAdd(&g_sums[base + 2], s.z); atomicAdd(&g_sums[base + 3], s.w);
            atomicMax(&g_maxenc[base + 0], enc_max(m.x));
            atomicMax(&g_maxenc[base + 1], enc_max(m.y));
            atomicMax(&g_maxenc[base + 2], enc_max(m.z));
            atomicMax(&g_maxenc[base + 3], enc_max(m.w));
            if (lane == 0) atomicAdd(&g_cnt[cur], cnt);
            s = make_float4(0.f, 0.f, 0.f, 0.f);
            m = make_float4(-INFINITY, -INFINITY, -INFINITY, -INFINITY);
            cnt = 0;
            cur = b;
        }
        float4 v = ((const float4*)(g_agg + (size_t)node * FDIM))[lane];
        s.x += v.x; s.y += v.y; s.z += v.z; s.w += v.w;
        m.x = fmaxf(m.x, v.x); m.y = fmaxf(m.y, v.y);
        m.z = fmaxf(m.z, v.z); m.w = fmaxf(m.w, v.w);
        cnt++;
    }
    int base = cur * FDIM + lane * 4;
    atomicAdd(&g_sums[base + 0], s.x); atomicAdd(&g_sums[base + 1], s.y);
    atomicAdd(&g_sums[base + 2], s.z); atomicAdd(&g_sums[base + 3], s.w);
    atomicMax(&g_maxenc[base + 0], enc_max(m.x));
    atomicMax(&g_maxenc[base + 1], enc_max(m.y));
    atomicMax(&g_maxenc[base + 2], enc_max(m.z));
    atomicMax(&g_maxenc[base + 3], enc_max(m.w));
    if (lane == 0) atomicAdd(&g_cnt[cur], cnt);
}

// ---------------- classifier head -------------------------------------------
__global__ void classifier_kernel(const float* __restrict__ Wc1, const float* __restrict__ bc1,
                                  const float* __restrict__ Wc2, const float* __restrict__ bc2,
                                  float* __restrict__ out) {
    int g = blockIdx.x, t = threadIdx.x;
    __shared__ float gv[256];
    __shared__ float hs[128];

    int cnt = g_cnt[g];
    float inv = 1.0f / (float)max(cnt, 1);
    gv[t] = g_sums[g * FDIM + t] * inv;
    unsigned e = g_maxenc[g * FDIM + t];
    gv[128 + t] = (cnt == 0) ? 0.0f : dec_max(e);
    __syncthreads();

    float acc = bc1[t];
#pragma unroll 8
    for (int k = 0; k < 256; k++) acc += gv[k] * Wc1[k * 128 + t];
    hs[t] = fmaxf(acc, 0.0f);
    __syncthreads();

    if (t < 10) {
        float o = bc2[t];
#pragma unroll 8
        for (int k = 0; k < 128; k++) o += hs[k] * Wc2[k * 10 + t];
        out[g * 10 + t] = o;
    }
}

// ---------------- launch -----------------------------------------------------
static inline int agg_blocks(int n0, int n1) { return ((n1 - n0) * 32 + 255) / 256; }

extern "C" void kernel_launch(void* const* d_in, const int* in_sizes, int n_in,
                              void* d_out, int out_size) {
    const float* x     = (const float*)d_in[0];
    const int*   ei    = (const int*)d_in[1];
    const int*   src   = ei;
    const int*   dst   = ei + N_EDGES;
    const int*   batch = (const int*)d_in[2];
    const float* W1 = (const float*)d_in[3];  const float* b1 = (const float*)d_in[4];
    const float* W2 = (const float*)d_in[5];  const float* b2 = (const float*)d_in[6];
    const float* W3 = (const float*)d_in[7];  const float* b3 = (const float*)d_in[8];
    const float* Wc1 = (const float*)d_in[9]; const float* bc1 = (const float*)d_in[10];
    const float* Wc2 = (const float*)d_in[11]; const float* bc2 = (const float*)d_in[12];
    float* out = (float*)d_out;

    static cudaStream_t sB = nullptr;
    static cudaEvent_t evFork, evPre, evG2d, evG3d, evFin;
    static cudaEvent_t evA1[NCHUNK], evA2[NCHUNK], evA3[NCHUNK];
    if (sB == nullptr) {
        cudaStreamCreateWithFlags(&sB, cudaStreamNonBlocking);
        cudaEventCreateWithFlags(&evFork, cudaEventDisableTiming);
        cudaEventCreateWithFlags(&evPre,  cudaEventDisableTiming);
        cudaEventCreateWithFlags(&evG2d,  cudaEventDisableTiming);
        cudaEventCreateWithFlags(&evG3d,  cudaEventDisableTiming);
        cudaEventCreateWithFlags(&evFin,  cudaEventDisableTiming);
        for (int j = 0; j < NCHUNK; j++) {
            cudaEventCreateWithFlags(&evA1[j], cudaEventDisableTiming);
            cudaEventCreateWithFlags(&evA2[j], cudaEventDisableTiming);
            cudaEventCreateWithFlags(&evA3[j], cudaEventDisableTiming);
        }
        cudaFuncSetAttribute(gemm_bf16, cudaFuncAttributeMaxDynamicSharedMemorySize,
                             SMEM_G);
    }

    float* hA; cudaGetSymbolAddress((void**)&hA, g_hA);
    float* ag; cudaGetSymbolAddress((void**)&ag, g_agg);
    __nv_bfloat16* ah; cudaGetSymbolAddress((void**)&ah, g_ah);
    __nv_bfloat16* al; cudaGetSymbolAddress((void**)&al, g_al);
    __nv_bfloat16* wth; cudaGetSymbolAddress((void**)&wth, g_wth);
    __nv_bfloat16* wtl; cudaGetSymbolAddress((void**)&wtl, g_wtl);

    // fork: preprocessing on sB concurrent with split_w + split_x + G1 on main
    cudaEventRecord(evFork, 0);
    cudaStreamWaitEvent(sB, evFork, 0);

    zero_kernel<<<(N_NODES + 255) / 256, 256, 0, sB>>>();
    hist_kernel<<<2048, 256, 0, sB>>>(dst);
    scan_part<<<SCAN_BLOCKS, 256, 0, sB>>>();
    scan_mid<<<1, 256, 0, sB>>>();
    scan_final<<<SCAN_BLOCKS, 256, 0, sB>>>();
    scatter_kernel<<<2048, 256, 0, sB>>>(src, dst);
    cudaEventRecord(evPre, sB);

    split_w<<<(3 * FDIM * FDIM + 255) / 256, 256>>>(W1, W2, W3);
    split_x<<<(N_NODES * FDIM / 4 + 255) / 256, 256>>>(x);
    gemm_bf16<<<(N_NODES + 127) / 128, 256, SMEM_G>>>(ah, al, wth, wtl, hA, 0);  // G1

    cudaStreamWaitEvent(0, evPre, 0);                       // A1 needs CSR

    // ---- A1 (reads hA -> ah/al[j]) on main ∥ G2 (ah/al[j] -> agg[j]) on sB ----
    for (int j = 0; j < NCHUNK; j++) {
        agg_split<<<agg_blocks(CH[j], CH[j + 1]), 256>>>(hA, b1, CH[j], CH[j + 1]);
        cudaEventRecord(evA1[j], 0);
        cudaStreamWaitEvent(sB, evA1[j], 0);
        int gb = (CH[j + 1] - CH[j] + 127) / 128;
        gemm_bf16<<<gb, 256, SMEM_G, sB>>>(ah, al, wth + FDIM * FDIM,
                                           wtl + FDIM * FDIM, ag, CH[j]);
    }
    cudaEventRecord(evG2d, sB);
    cudaStreamWaitEvent(0, evG2d, 0);                       // A2 gathers all of agg

    // ---- A2 (reads agg -> ah/al[j]) on main ∥ G3 (ah/al[j] -> hA[j]) on sB ----
    for (int j = 0; j < NCHUNK; j++) {
        agg_split<<<agg_blocks(CH[j], CH[j + 1]), 256>>>(ag, b2, CH[j], CH[j + 1]);
        cudaEventRecord(evA2[j], 0);
        cudaStreamWaitEvent(sB, evA2[j], 0);
        int gb = (CH[j + 1] - CH[j] + 127) / 128;
        gemm_bf16<<<gb, 256, SMEM_G, sB>>>(ah, al, wth + 2 * FDIM * FDIM,
                                           wtl + 2 * FDIM * FDIM, hA, CH[j]);
    }
    cudaEventRecord(evG3d, sB);
    cudaStreamWaitEvent(0, evG3d, 0);                       // A3 gathers all of hA

    // ---- A3 (reads hA -> agg[j]) on main ∥ pool (agg[j]) on sB ----
    for (int j = 0; j < NCHUNK; j++) {
        agg_f32<<<agg_blocks(CH[j], CH[j + 1]), 256>>>(hA, b3, ag, CH[j], CH[j + 1]);
        cudaEventRecord(evA3[j], 0);
        cudaStreamWaitEvent(sB, evA3[j], 0);
        int warps = (CH[j + 1] - CH[j] + 31) / 32;
        pool_kernel<<<(warps * 32 + 255) / 256, 256, 0, sB>>>(batch, CH[j], CH[j + 1]);
    }
    classifier_kernel<<<N_GRAPHS, 128, 0, sB>>>(Wc1, bc1, Wc2, bc2, out);
    cudaEventRecord(evFin, sB);
    cudaStreamWaitEvent(0, evFin, 0);                       // join back to main
}

// round 16
// speedup vs baseline: 1.2916x; 1.2916x over previous
#include <cuda_runtime.h>
#include <cuda_bf16.h>
#include <cuda_fp16.h>
#include <cstdint>

#define N_NODES 100000
#define N_EDGES 1600000
#define N_GRAPHS 512
#define FDIM 128
#define SCAN_CHUNK 512
#define SCAN_BLOCKS ((N_NODES + SCAN_CHUNK - 1) / SCAN_CHUNK)   // 196
#define SMS 24
#define WS2 136
#define SMEM_G ((3072 * 2 + 17408 * 2) * 2)   // 81920 B

// ---------------- device scratch (allocation-free: __device__ globals) ------
__device__ __align__(16) __half g_h16[(size_t)N_NODES * FDIM];  // conv pre-act (fp16)
__device__ float    g_agg[(size_t)N_NODES * FDIM];
__device__ __align__(16) __nv_bfloat16 g_ah[(size_t)N_NODES * FDIM];
__device__ __align__(16) __nv_bfloat16 g_al[(size_t)N_NODES * FDIM];
__device__ __align__(16) __nv_bfloat16 g_wth[3][FDIM * FDIM];
__device__ __align__(16) __nv_bfloat16 g_wtl[3][FDIM * FDIM];
__device__ int      g_deg[N_NODES];
__device__ int      g_cursor[N_NODES];
__device__ float    g_dinv[N_NODES];
__device__ int      g_rowoff[N_NODES + 1];
__device__ unsigned long long g_edge[N_EDGES];
__device__ int      g_part[SCAN_BLOCKS];
__device__ float    g_sums[N_GRAPHS * FDIM];
__device__ unsigned g_maxenc[N_GRAPHS * FDIM];
__device__ int      g_cnt[N_GRAPHS];

// ---------------- helpers ---------------------------------------------------
__device__ __forceinline__ unsigned enc_max(float f) {
    unsigned u = __float_as_uint(f);
    return (u & 0x80000000u) ? ~u : (u | 0x80000000u);
}
__device__ __forceinline__ float dec_max(unsigned e) {
    unsigned bits = (e & 0x80000000u) ? (e ^ 0x80000000u) : ~e;
    return __uint_as_float(bits);
}
__device__ __forceinline__ void mma_bf16(float* c, const uint32_t* a,
                                         uint32_t b0, uint32_t b1) {
    asm volatile(
        "mma.sync.aligned.m16n8k16.row.col.f32.bf16.bf16.f32 "
        "{%0,%1,%2,%3}, {%4,%5,%6,%7}, {%8,%9}, {%0,%1,%2,%3};"
        : "+f"(c[0]), "+f"(c[1]), "+f"(c[2]), "+f"(c[3])
        : "r"(a[0]), "r"(a[1]), "r"(a[2]), "r"(a[3]), "r"(b0), "r"(b1));
}
__device__ __forceinline__ uint32_t pack_hi2(float v0, float v1, float& h0f, float& h1f) {
    __nv_bfloat16 h0 = __float2bfloat16(v0), h1 = __float2bfloat16(v1);
    h0f = __bfloat162float(h0); h1f = __bfloat162float(h1);
    __nv_bfloat162 p; p.x = h0; p.y = h1;
    return *(uint32_t*)&p;
}
__device__ __forceinline__ uint32_t pack_bf2(float v0, float v1) {
    __nv_bfloat162 p; p.x = __float2bfloat16(v0); p.y = __float2bfloat16(v1);
    return *(uint32_t*)&p;
}

// ---------------- preprocessing ---------------------------------------------
__global__ void zero_kernel() {
    int i = blockIdx.x * blockDim.x + threadIdx.x;
    if (i < N_GRAPHS * FDIM) { g_sums[i] = 0.0f; g_maxenc[i] = 0u; }
    if (i < N_GRAPHS) g_cnt[i] = 0;
    if (i < N_NODES) g_deg[i] = 0;
}

__global__ void hist_kernel(const int* __restrict__ dst) {
    int stride = gridDim.x * blockDim.x;
    for (int e = blockIdx.x * blockDim.x + threadIdx.x; e < N_EDGES; e += stride)
        atomicAdd(&g_deg[dst[e]], 1);
}

__global__ void scan_part() {
    int b = blockIdx.x, t = threadIdx.x;
    int base = b * SCAN_CHUNK;
    int s = 0;
    for (int i = t; i < SCAN_CHUNK; i += 256) {
        int idx = base + i;
        if (idx < N_NODES) s += g_deg[idx];
    }
    __shared__ int sh[8];
#pragma unroll
    for (int o = 16; o; o >>= 1) s += __shfl_down_sync(~0u, s, o);
    if ((t & 31) == 0) sh[t >> 5] = s;
    __syncthreads();
    if (t < 8) {
        int v = sh[t];
#pragma unroll
        for (int o = 4; o; o >>= 1) v += __shfl_down_sync(0xffu, v, o);
        if (t == 0) g_part[b] = v;
    }
}

__global__ void scan_mid() {
    __shared__ int sh[256];
    int t = threadIdx.x;
    int v = (t < SCAN_BLOCKS) ? g_part[t] : 0;
    sh[t] = v;
    __syncthreads();
    for (int o = 1; o < 256; o <<= 1) {
        int u = (t >= o) ? sh[t - o] : 0;
        __syncthreads();
        sh[t] += u;
        __syncthreads();
    }
    if (t < SCAN_BLOCKS) g_part[t] = sh[t] - v;
    if (t == 0) g_rowoff[N_NODES] = N_EDGES;
}

__global__ void scan_final() {
    int b = blockIdx.x, t = threadIdx.x;
    int base = b * SCAN_CHUNK;
    int i0 = base + 2 * t, i1 = i0 + 1;
    int d0 = (i0 < N_NODES) ? g_deg[i0] : 0;
    int d1 = (i1 < N_NODES) ? g_deg[i1] : 0;
    int s = d0 + d1;
    __shared__ int sh[256];
    sh[t] = s;
    __syncthreads();
    for (int o = 1; o < 256; o <<= 1) {
        int u = (t >= o) ? sh[t - o] : 0;
        __syncthreads();
        sh[t] += u;
        __syncthreads();
    }
    int excl = sh[t] - s + g_part[b];
    if (i0 < N_NODES) {
        g_rowoff[i0] = excl;
        g_dinv[i0] = rsqrtf((float)d0 + 1.0f);
        g_cursor[i0] = 0;
    }
    if (i1 < N_NODES) {
        g_rowoff[i1] = excl + d0;
        g_dinv[i1] = rsqrtf((float)d1 + 1.0f);
        g_cursor[i1] = 0;
    }
}

__global__ void scatter_kernel(const int* __restrict__ src, const int* __restrict__ dst) {
    int stride = gridDim.x * blockDim.x;
    for (int e = blockIdx.x * blockDim.x + threadIdx.x; e < N_EDGES; e += stride) {
        int s = src[e], d = dst[e];
        int pos = g_rowoff[d] + atomicAdd(&g_cursor[d], 1);
        float norm = g_dinv[s] * g_dinv[d];
        g_edge[pos] = (unsigned long long)(unsigned)s |
                      ((unsigned long long)__float_as_uint(norm) << 32);
    }
}

// ---------------- weight split ----------------------------------------------
__global__ void split_w(const float* __restrict__ W1, const float* __restrict__ W2,
                        const float* __restrict__ W3) {
    int t = blockIdx.x * blockDim.x + threadIdx.x;
    if (t >= 3 * FDIM * FDIM) return;
    int l = t >> 14, i = t & 16383;
    int k = i >> 7, n = i & 127;
    const float* W = (l == 0) ? W1 : (l == 1) ? W2 : W3;
    float v = W[k * FDIM + n];
    __nv_bfloat16 h = __float2bfloat16(v);
    g_wth[l][n * FDIM + k] = h;
    g_wtl[l][n * FDIM + k] = __float2bfloat16(v - __bfloat162float(h));
}

__global__ void split_x(const float* __restrict__ x) {
    int i = blockIdx.x * blockDim.x + threadIdx.x;
    if (i >= N_NODES * FDIM / 4) return;
    float4 v = ((const float4*)x)[i];
    float h0, h1, h2, h3;
    uint32_t p01 = pack_hi2(v.x, v.y, h0, h1);
    uint32_t p23 = pack_hi2(v.z, v.w, h2, h3);
    *(uint2*)&g_ah[(size_t)i * 4] = make_uint2(p01, p23);
    *(uint2*)&g_al[(size_t)i * 4] =
        make_uint2(pack_bf2(v.x - h0, v.y - h1), pack_bf2(v.z - h2, v.w - h3));
}

// ---------------- HMMA GEMM (pre-split bf16): out(fp16) = A @ W -------------
__global__ void __launch_bounds__(256)
gemm_bf16(const __nv_bfloat16* __restrict__ Ah, const __nv_bfloat16* __restrict__ Al,
          const __nv_bfloat16* __restrict__ Wth, const __nv_bfloat16* __restrict__ Wtl,
          __half* __restrict__ out) {
    extern __shared__ __nv_bfloat16 sm[];
    __nv_bfloat16* Ahs = sm;
    __nv_bfloat16* Als = sm + 3072;
    __nv_bfloat16* Wsh = sm + 6144;
    __nv_bfloat16* Wsl = sm + 6144 + 17408;

    int tid = threadIdx.x, warp = tid >> 5, lane = tid & 31;
    int g = lane >> 2, q = lane & 3;
    int row0 = blockIdx.x * 128;

#pragma unroll
    for (int i = 0; i < 8; i++) {
        int idx = tid + i * 256;
        int n = idx >> 4, s = idx & 15;
        *(uint4*)&Wsh[n * WS2 + s * 8] = *(const uint4*)&Wth[n * FDIM + s * 8];
        *(uint4*)&Wsl[n * WS2 + s * 8] = *(const uint4*)&Wtl[n * FDIM + s * 8];
    }

    float acc[16][4];
#pragma unroll
    for (int nt = 0; nt < 16; nt++)
#pragma unroll
        for (int j = 0; j < 4; j++) acc[nt][j] = 0.0f;

    for (int ks = 0; ks < 8; ks++) {
        __syncthreads();
        {
            int r = tid >> 1, hf = tid & 1;
            int gr = row0 + r;
            if (gr >= N_NODES) gr = N_NODES - 1;
            size_t go = (size_t)gr * FDIM + ks * 16 + hf * 8;
            *(uint4*)&Ahs[r * SMS + hf * 8] = *(const uint4*)&Ah[go];
            *(uint4*)&Als[r * SMS + hf * 8] = *(const uint4*)&Al[go];
        }
        __syncthreads();

        int r0 = (warp * 16 + g) * SMS, r1 = r0 + 8 * SMS;
        uint32_t ah[4], al[4];
        ah[0] = *(const uint32_t*)&Ahs[r0 + q * 2];
        ah[1] = *(const uint32_t*)&Ahs[r1 + q * 2];
        ah[2] = *(const uint32_t*)&Ahs[r0 + q * 2 + 8];
        ah[3] = *(const uint32_t*)&Ahs[r1 + q * 2 + 8];
        al[0] = *(const uint32_t*)&Als[r0 + q * 2];
        al[1] = *(const uint32_t*)&Als[r1 + q * 2];
        al[2] = *(const uint32_t*)&Als[r0 + q * 2 + 8];
        al[3] = *(const uint32_t*)&Als[r1 + q * 2 + 8];

#pragma unroll
        for (int nt = 0; nt < 16; nt++) {
            int nb = (nt * 8 + g) * WS2 + ks * 16;
            uint32_t bh0 = *(const uint32_t*)&Wsh[nb + q * 2];
            uint32_t bh1 = *(const uint32_t*)&Wsh[nb + q * 2 + 8];
            uint32_t bl0 = *(const uint32_t*)&Wsl[nb + q * 2];
            uint32_t bl1 = *(const uint32_t*)&Wsl[nb + q * 2 + 8];
            mma_bf16(acc[nt], ah, bh0, bh1);
            mma_bf16(acc[nt], ah, bl0, bl1);
            mma_bf16(acc[nt], al, bh0, bh1);
        }
    }

    int rowa = row0 + warp * 16 + g;
    int rowb = rowa + 8;
#pragma unroll
    for (int nt = 0; nt < 16; nt++) {
        int col = nt * 8 + q * 2;
        if (rowa < N_NODES)
            *(__half2*)(out + (size_t)rowa * FDIM + col) =
                __floats2half2_rn(acc[nt][0], acc[nt][1]);
        if (rowb < N_NODES)
            *(__half2*)(out + (size_t)rowb * FDIM + col) =
                __floats2half2_rn(acc[nt][2], acc[nt][3]);
    }
}

// ---------------- aggregation core (fp16 gather, fp32 accumulate) -----------
__device__ __forceinline__ float4 agg_row(const __half* __restrict__ h,
                                          const float* __restrict__ bias,
                                          int node, int lane) {
    float di = g_dinv[node];
    float sc = di * di;
    float4 b4 = ((const float4*)bias)[lane];
    uint2 hraw = *(const uint2*)(h + (size_t)node * FDIM + lane * 4);
    float2 f01 = __half22float2(*(__half2*)&hraw.x);
    float2 f23 = __half22float2(*(__half2*)&hraw.y);
    float4 acc;
    acc.x = b4.x + f01.x * sc; acc.y = b4.y + f01.y * sc;
    acc.z = b4.z + f23.x * sc; acc.w = b4.w + f23.y * sc;

    int beg = g_rowoff[node];
    int deg = g_rowoff[node + 1] - beg;
    for (int base = 0; base < deg; base += 32) {
        int n = deg - base; if (n > 32) n = 32;
        unsigned lo = 0, hi = 0;
        if (base + lane < deg) {
            unsigned long long e = __ldg(&g_edge[beg + base + lane]);
            lo = (unsigned)e;
            hi = (unsigned)(e >> 32);
        }
#pragma unroll 4
        for (int j = 0; j < n; j++) {
            int s = (int)__shfl_sync(~0u, lo, j);
            float w = __uint_as_float(__shfl_sync(~0u, hi, j));
            uint2 vr = __ldg((const uint2*)(h + (size_t)s * FDIM) + lane);
            float2 v01 = __half22float2(*(__half2*)&vr.x);
            float2 v23 = __half22float2(*(__half2*)&vr.y);
            acc.x += w * v01.x; acc.y += w * v01.y;
            acc.z += w * v23.x; acc.w += w * v23.y;
        }
    }
    return acc;
}

// conv-1/2 flavor: emit relu'd bf16 hi/lo for next GEMM
__global__ void agg_split(const __half* __restrict__ h, const float* __restrict__ bias) {
    int warpid = (blockIdx.x * blockDim.x + threadIdx.x) >> 5;
    int lane = threadIdx.x & 31;
    if (warpid >= N_NODES) return;
    float4 a = agg_row(h, bias, warpid, lane);
    a.x = fmaxf(a.x, 0.f); a.y = fmaxf(a.y, 0.f);
    a.z = fmaxf(a.z, 0.f); a.w = fmaxf(a.w, 0.f);
    float h0, h1, h2, h3;
    uint32_t p01 = pack_hi2(a.x, a.y, h0, h1);
    uint32_t p23 = pack_hi2(a.z, a.w, h2, h3);
    size_t o = (size_t)warpid * FDIM + lane * 4;
    *(uint2*)&g_ah[o] = make_uint2(p01, p23);
    *(uint2*)&g_al[o] =
        make_uint2(pack_bf2(a.x - h0, a.y - h1), pack_bf2(a.z - h2, a.w - h3));
}

// conv-3 flavor: fp32 for pooling
__global__ void agg_f32(const __half* __restrict__ h, const float* __restrict__ bias,
                        float* __restrict__ out) {
    int warpid = (blockIdx.x * blockDim.x + threadIdx.x) >> 5;
    int lane = threadIdx.x & 31;
    if (warpid >= N_NODES) return;
    float4 a = agg_row(h, bias, warpid, lane);
    ((float4*)(out + (size_t)warpid * FDIM))[lane] = a;
}

// ---------------- pooling ----------------------------------------------------
__global__ void pool_kernel(const int* __restrict__ batch) {
    int warpid = (blockIdx.x * blockDim.x + threadIdx.x) >> 5;
    int lane = threadIdx.x & 31;
    int beg = warpid * 32;
    if (beg >= N_NODES) return;
    int end = min(beg + 32, N_NODES);

    int cur = batch[beg];
    float4 s = make_float4(0.f, 0.f, 0.f, 0.f);
    float4 m = make_float4(-INFINITY, -INFINITY, -INFINITY, -INFINITY);
    int cnt = 0;

    for (int node = beg; node < end; node++) {
        int b = batch[node];
        if (b != cur) {
            int base = cur * FDIM + lane * 4;
            atomicAdd(&g_sums[base + 0], s.x); atomicAdd(&g_sums[base + 1], s.y);
            atomicAdd(&g_sums[base + 2], s.z); atomicAdd(&g_sums[base + 3], s.w);
            atomicMax(&g_maxenc[base + 0], enc_max(m.x));
            atomicMax(&g_maxenc[base + 1], enc_max(m.y));
            atomicMax(&g_maxenc[base + 2], enc_max(m.z));
            atomicMax(&g_maxenc[base + 3], enc_max(m.w));
            if (lane == 0) atomicAdd(&g_cnt[cur], cnt);
            s = make_float4(0.f, 0.f, 0.f, 0.f);
            m = make_float4(-INFINITY, -INFINITY, -INFINITY, -INFINITY);
            cnt = 0;
            cur = b;
        }
        float4 v = ((const float4*)(g_agg + (size_t)node * FDIM))[lane];
        s.x += v.x; s.y += v.y; s.z += v.z; s.w += v.w;
        m.x = fmaxf(m.x, v.x); m.y = fmaxf(m.y, v.y);
        m.z = fmaxf(m.z, v.z); m.w = fmaxf(m.w, v.w);
        cnt++;
    }
    int base = cur * FDIM + lane * 4;
    atomicAdd(&g_sums[base + 0], s.x); atomicAdd(&g_sums[base + 1], s.y);
    atomicAdd(&g_sums[base + 2], s.z); atomicAdd(&g_sums[base + 3], s.w);
    atomicMax(&g_maxenc[base + 0], enc_max(m.x));
    atomicMax(&g_maxenc[base + 1], enc_max(m.y));
    atomicMax(&g_maxenc[base + 2], enc_max(m.z));
    atomicMax(&g_maxenc[base + 3], enc_max(m.w));
    if (lane == 0) atomicAdd(&g_cnt[cur], cnt);
}

// ---------------- classifier head -------------------------------------------
__global__ void classifier_kernel(const float* __restrict__ Wc1, const float* __restrict__ bc1,
                                  const float* __restrict__ Wc2, const float* __restrict__ bc2,
                                  float* __restrict__ out) {
    int g = blockIdx.x, t = threadIdx.x;
    __shared__ float gv[256];
    __shared__ float hs[128];

    int cnt = g_cnt[g];
    float inv = 1.0f / (float)max(cnt, 1);
    gv[t] = g_sums[g * FDIM + t] * inv;
    unsigned e = g_maxenc[g * FDIM + t];
    gv[128 + t] = (cnt == 0) ? 0.0f : dec_max(e);
    __syncthreads();

    float acc = bc1[t];
#pragma unroll 8
    for (int k = 0; k < 256; k++) acc += gv[k] * Wc1[k * 128 + t];
    hs[t] = fmaxf(acc, 0.0f);
    __syncthreads();

    if (t < 10) {
        float o = bc2[t];
#pragma unroll 8
        for (int k = 0; k < 128; k++) o += hs[k] * Wc2[k * 10 + t];
        out[g * 10 + t] = o;
    }
}

// ---------------- launch -----------------------------------------------------
extern "C" void kernel_launch(void* const* d_in, const int* in_sizes, int n_in,
                              void* d_out, int out_size) {
    const float* x     = (const float*)d_in[0];
    const int*   ei    = (const int*)d_in[1];
    const int*   src   = ei;
    const int*   dst   = ei + N_EDGES;
    const int*   batch = (const int*)d_in[2];
    const float* W1 = (const float*)d_in[3];  const float* b1 = (const float*)d_in[4];
    const float* W2 = (const float*)d_in[5];  const float* b2 = (const float*)d_in[6];
    const float* W3 = (const float*)d_in[7];  const float* b3 = (const float*)d_in[8];
    const float* Wc1 = (const float*)d_in[9]; const float* bc1 = (const float*)d_in[10];
    const float* Wc2 = (const float*)d_in[11]; const float* bc2 = (const float*)d_in[12];
    float* out = (float*)d_out;

    static cudaStream_t s2 = nullptr;
    static cudaEvent_t ev_fork = nullptr, ev_join = nullptr;
    if (s2 == nullptr) {
        cudaStreamCreateWithFlags(&s2, cudaStreamNonBlocking);
        cudaEventCreateWithFlags(&ev_fork, cudaEventDisableTiming);
        cudaEventCreateWithFlags(&ev_join, cudaEventDisableTiming);
        cudaFuncSetAttribute(gemm_bf16, cudaFuncAttributeMaxDynamicSharedMemorySize,
                             SMEM_G);
    }

    float* ag; cudaGetSymbolAddress((void**)&ag, g_agg);
    __half* h16; cudaGetSymbolAddress((void**)&h16, g_h16);
    __nv_bfloat16* ah; cudaGetSymbolAddress((void**)&ah, g_ah);
    __nv_bfloat16* al; cudaGetSymbolAddress((void**)&al, g_al);
    __nv_bfloat16* wth; cudaGetSymbolAddress((void**)&wth, g_wth);
    __nv_bfloat16* wtl; cudaGetSymbolAddress((void**)&wtl, g_wtl);

    const int GEMM_BLOCKS = (N_NODES + 127) / 128;          // 782
    const int AGG_BLOCKS  = (N_NODES * 32 + 255) / 256;     // 12500

    // fork: preprocessing on s2 concurrent with splits + G1 on main
    cudaEventRecord(ev_fork, 0);
    cudaStreamWaitEvent(s2, ev_fork, 0);

    zero_kernel<<<(N_NODES + 255) / 256, 256, 0, s2>>>();
    hist_kernel<<<2048, 256, 0, s2>>>(dst);
    scan_part<<<SCAN_BLOCKS, 256, 0, s2>>>();
    scan_mid<<<1, 256, 0, s2>>>();
    scan_final<<<SCAN_BLOCKS, 256, 0, s2>>>();
    scatter_kernel<<<2048, 256, 0, s2>>>(src, dst);
    cudaEventRecord(ev_join, s2);

    split_w<<<(3 * FDIM * FDIM + 255) / 256, 256>>>(W1, W2, W3);
    split_x<<<(N_NODES * FDIM / 4 + 255) / 256, 256>>>(x);
    gemm_bf16<<<GEMM_BLOCKS, 256, SMEM_G>>>(ah, al, wth, wtl, h16);         // G1

    cudaStreamWaitEvent(0, ev_join, 0);                     // A1 needs CSR

    agg_split<<<AGG_BLOCKS, 256>>>(h16, b1);                // A1 -> bf16 hi/lo
    gemm_bf16<<<GEMM_BLOCKS, 256, SMEM_G>>>(ah, al, wth + FDIM * FDIM,
                                            wtl + FDIM * FDIM, h16);        // G2
    agg_split<<<AGG_BLOCKS, 256>>>(h16, b2);                // A2 -> bf16 hi/lo
    gemm_bf16<<<GEMM_BLOCKS, 256, SMEM_G>>>(ah, al, wth + 2 * FDIM * FDIM,
                                            wtl + 2 * FDIM * FDIM, h16);    // G3
    agg_f32<<<AGG_BLOCKS, 256>>>(h16, b3, ag);              // A3 -> fp32

    int pool_warps = (N_NODES + 31) / 32;
    pool_kernel<<<(pool_warps * 32 + 255) / 256, 256>>>(batch);
    classifier_kernel<<<N_GRAPHS, 128>>>(Wc1, bc1, Wc2, bc2, out);
}

// round 17
// speedup vs baseline: 1.4189x; 1.0986x over previous
#include <cuda_runtime.h>
#include <cuda_fp16.h>
#include <cstdint>

#define N_NODES 100000
#define N_EDGES 1600000
#define N_GRAPHS 512
#define FDIM 128
#define SCAN_CHUNK 512
#define SCAN_BLOCKS ((N_NODES + SCAN_CHUNK - 1) / SCAN_CHUNK)   // 196
#define SMS 24        // A smem row stride (half) — proven conflict pattern
#define WS2 136       // W smem row stride (half) — proven conflict pattern
#define SMEM_G ((3072 + 17408 * 2) * 2)   // 75776 B (halves: As 3072, Wh/Wl 17408 each)

// ---------------- device scratch (allocation-free: __device__ globals) ------
__device__ __align__(16) __half g_a16[(size_t)N_NODES * FDIM];  // GEMM input (fp16)
__device__ __align__(16) __half g_h16[(size_t)N_NODES * FDIM];  // GEMM output (fp16)
__device__ float    g_agg[(size_t)N_NODES * FDIM];
__device__ __align__(16) __half g_wh[3][FDIM * FDIM];           // W^T hi (fp16)
__device__ __align__(16) __half g_wl[3][FDIM * FDIM];           // W^T lo (fp16)
__device__ int      g_deg[N_NODES];
__device__ float    g_dinv[N_NODES];
__device__ int      g_rowoff[N_NODES + 1];
__device__ int      g_rank[N_EDGES];
__device__ unsigned long long g_edge[N_EDGES];   // (norm<<32)|src
__device__ int      g_part[SCAN_BLOCKS];
__device__ float    g_sums[N_GRAPHS * FDIM];
__device__ unsigned g_maxenc[N_GRAPHS * FDIM];
__device__ int      g_cnt[N_GRAPHS];

// ---------------- helpers ---------------------------------------------------
__device__ __forceinline__ unsigned enc_max(float f) {
    unsigned u = __float_as_uint(f);
    return (u & 0x80000000u) ? ~u : (u | 0x80000000u);
}
__device__ __forceinline__ float dec_max(unsigned e) {
    unsigned bits = (e & 0x80000000u) ? (e ^ 0x80000000u) : ~e;
    return __uint_as_float(bits);
}
__device__ __forceinline__ void mma_f16(float* c, const uint32_t* a,
                                        uint32_t b0, uint32_t b1) {
    asm volatile(
        "mma.sync.aligned.m16n8k16.row.col.f32.f16.f16.f32 "
        "{%0,%1,%2,%3}, {%4,%5,%6,%7}, {%8,%9}, {%0,%1,%2,%3};"
        : "+f"(c[0]), "+f"(c[1]), "+f"(c[2]), "+f"(c[3])
        : "r"(a[0]), "r"(a[1]), "r"(a[2]), "r"(a[3]), "r"(b0), "r"(b1));
}

// ---------------- preprocessing ---------------------------------------------
__global__ void zero_kernel() {
    int i = blockIdx.x * blockDim.x + threadIdx.x;
    if (i < N_GRAPHS * FDIM) { g_sums[i] = 0.0f; g_maxenc[i] = 0u; }
    if (i < N_GRAPHS) g_cnt[i] = 0;
    if (i < N_NODES) g_deg[i] = 0;
}

// histogram + per-edge rank (atomicAdd return value), coalesced rank store
__global__ void hist_kernel(const int* __restrict__ dst) {
    int stride = gridDim.x * blockDim.x;
    for (int e = blockIdx.x * blockDim.x + threadIdx.x; e < N_EDGES; e += stride)
        g_rank[e] = atomicAdd(&g_deg[dst[e]], 1);
}

__global__ void scan_part() {
    int b = blockIdx.x, t = threadIdx.x;
    int base = b * SCAN_CHUNK;
    int s = 0;
    for (int i = t; i < SCAN_CHUNK; i += 256) {
        int idx = base + i;
        if (idx < N_NODES) s += g_deg[idx];
    }
    __shared__ int sh[8];
#pragma unroll
    for (int o = 16; o; o >>= 1) s += __shfl_down_sync(~0u, s, o);
    if ((t & 31) == 0) sh[t >> 5] = s;
    __syncthreads();
    if (t < 8) {
        int v = sh[t];
#pragma unroll
        for (int o = 4; o; o >>= 1) v += __shfl_down_sync(0xffu, v, o);
        if (t == 0) g_part[b] = v;
    }
}

__global__ void scan_mid() {
    __shared__ int sh[256];
    int t = threadIdx.x;
    int v = (t < SCAN_BLOCKS) ? g_part[t] : 0;
    sh[t] = v;
    __syncthreads();
    for (int o = 1; o < 256; o <<= 1) {
        int u = (t >= o) ? sh[t - o] : 0;
        __syncthreads();
        sh[t] += u;
        __syncthreads();
    }
    if (t < SCAN_BLOCKS) g_part[t] = sh[t] - v;
    if (t == 0) g_rowoff[N_NODES] = N_EDGES;
}

__global__ void scan_final() {
    int b = blockIdx.x, t = threadIdx.x;
    int base = b * SCAN_CHUNK;
    int i0 = base + 2 * t, i1 = i0 + 1;
    int d0 = (i0 < N_NODES) ? g_deg[i0] : 0;
    int d1 = (i1 < N_NODES) ? g_deg[i1] : 0;
    int s = d0 + d1;
    __shared__ int sh[256];
    sh[t] = s;
    __syncthreads();
    for (int o = 1; o < 256; o <<= 1) {
        int u = (t >= o) ? sh[t - o] : 0;
        __syncthreads();
        sh[t] += u;
        __syncthreads();
    }
    int excl = sh[t] - s + g_part[b];
    if (i0 < N_NODES) {
        g_rowoff[i0] = excl;
        g_dinv[i0] = rsqrtf((float)d0 + 1.0f);
    }
    if (i1 < N_NODES) {
        g_rowoff[i1] = excl + d0;
        g_dinv[i1] = rsqrtf((float)d1 + 1.0f);
    }
}

// atomic-free scatter using precomputed ranks
__global__ void scatter_kernel(const int* __restrict__ src, const int* __restrict__ dst) {
    int stride = gridDim.x * blockDim.x;
    for (int e = blockIdx.x * blockDim.x + threadIdx.x; e < N_EDGES; e += stride) {
        int s = src[e], d = dst[e];
        int pos = g_rowoff[d] + g_rank[e];
        float norm = g_dinv[s] * g_dinv[d];
        g_edge[pos] = (unsigned long long)(unsigned)s |
                      ((unsigned long long)__float_as_uint(norm) << 32);
    }
}

// ---------------- weight split: W^T fp16 hi/lo ------------------------------
__global__ void split_w(const float* __restrict__ W1, const float* __restrict__ W2,
                        const float* __restrict__ W3) {
    int t = blockIdx.x * blockDim.x + threadIdx.x;
    if (t >= 3 * FDIM * FDIM) return;
    int l = t >> 14, i = t & 16383;
    int k = i >> 7, n = i & 127;
    const float* W = (l == 0) ? W1 : (l == 1) ? W2 : W3;
    float v = W[k * FDIM + n];
    __half h = __float2half_rn(v);
    g_wh[l][n * FDIM + k] = h;
    g_wl[l][n * FDIM + k] = __float2half_rn(v - __half2float(h));
}

// ---------------- x -> fp16 --------------------------------------------------
__global__ void split_x(const float* __restrict__ x) {
    int i = blockIdx.x * blockDim.x + threadIdx.x;
    if (i >= N_NODES * FDIM / 4) return;
    float4 v = ((const float4*)x)[i];
    __half2 p0 = __floats2half2_rn(v.x, v.y);
    __half2 p1 = __floats2half2_rn(v.z, v.w);
    *(uint2*)&g_a16[(size_t)i * 4] = make_uint2(*(uint32_t*)&p0, *(uint32_t*)&p1);
}

// ---------------- HMMA GEMM: out(fp16) = A(fp16) @ (Wh+Wl) ------------------
__global__ void __launch_bounds__(256)
gemm_f16(const __half* __restrict__ A,
         const __half* __restrict__ Wh, const __half* __restrict__ Wl,
         __half* __restrict__ out) {
    extern __shared__ __half sm[];
    __half* As  = sm;                 // 128*24
    __half* Wsh = sm + 3072;          // 128*136
    __half* Wsl = sm + 3072 + 17408;  // 128*136

    int tid = threadIdx.x, warp = tid >> 5, lane = tid & 31;
    int g = lane >> 2, q = lane & 3;
    int row0 = blockIdx.x * 128;

    // load W hi/lo once
#pragma unroll
    for (int i = 0; i < 8; i++) {
        int idx = tid + i * 256;
        int n = idx >> 4, s = idx & 15;
        *(uint4*)&Wsh[n * WS2 + s * 8] = *(const uint4*)&Wh[n * FDIM + s * 8];
        *(uint4*)&Wsl[n * WS2 + s * 8] = *(const uint4*)&Wl[n * FDIM + s * 8];
    }

    float acc[16][4];
#pragma unroll
    for (int nt = 0; nt < 16; nt++)
#pragma unroll
        for (int j = 0; j < 4; j++) acc[nt][j] = 0.0f;

    for (int ks = 0; ks < 8; ks++) {
        __syncthreads();
        {
            int r = tid >> 1, hf = tid & 1;
            int gr = row0 + r;
            if (gr >= N_NODES) gr = N_NODES - 1;
            *(uint4*)&As[r * SMS + hf * 8] =
                *(const uint4*)&A[(size_t)gr * FDIM + ks * 16 + hf * 8];
        }
        __syncthreads();

        int r0 = (warp * 16 + g) * SMS, r1 = r0 + 8 * SMS;
        uint32_t a[4];
        a[0] = *(const uint32_t*)&As[r0 + q * 2];
        a[1] = *(const uint32_t*)&As[r1 + q * 2];
        a[2] = *(const uint32_t*)&As[r0 + q * 2 + 8];
        a[3] = *(const uint32_t*)&As[r1 + q * 2 + 8];

#pragma unroll
        for (int nt = 0; nt < 16; nt++) {
            int nb = (nt * 8 + g) * WS2 + ks * 16;
            uint32_t bh0 = *(const uint32_t*)&Wsh[nb + q * 2];
            uint32_t bh1 = *(const uint32_t*)&Wsh[nb + q * 2 + 8];
            uint32_t bl0 = *(const uint32_t*)&Wsl[nb + q * 2];
            uint32_t bl1 = *(const uint32_t*)&Wsl[nb + q * 2 + 8];
            mma_f16(acc[nt], a, bh0, bh1);
            mma_f16(acc[nt], a, bl0, bl1);
        }
    }

    int rowa = row0 + warp * 16 + g;
    int rowb = rowa + 8;
#pragma unroll
    for (int nt = 0; nt < 16; nt++) {
        int col = nt * 8 + q * 2;
        if (rowa < N_NODES)
            *(__half2*)(out + (size_t)rowa * FDIM + col) =
                __floats2half2_rn(acc[nt][0], acc[nt][1]);
        if (rowb < N_NODES)
            *(__half2*)(out + (size_t)rowb * FDIM + col) =
                __floats2half2_rn(acc[nt][2], acc[nt][3]);
    }
}

// ---------------- aggregation core (fp16 gather, fp32 accumulate) -----------
__device__ __forceinline__ float4 agg_row(const __half* __restrict__ h,
                                          const float* __restrict__ bias,
                                          int node, int lane) {
    float di = g_dinv[node];
    float sc = di * di;
    float4 b4 = ((const float4*)bias)[lane];
    uint2 hraw = *(const uint2*)(h + (size_t)node * FDIM + lane * 4);
    float2 f01 = __half22float2(*(__half2*)&hraw.x);
    float2 f23 = __half22float2(*(__half2*)&hraw.y);
    float4 acc;
    acc.x = b4.x + f01.x * sc; acc.y = b4.y + f01.y * sc;
    acc.z = b4.z + f23.x * sc; acc.w = b4.w + f23.y * sc;

    int beg = g_rowoff[node];
    int deg = g_rowoff[node + 1] - beg;
    for (int base = 0; base < deg; base += 32) {
        int n = deg - base; if (n > 32) n = 32;
        unsigned lo = 0, hi = 0;
        if (base + lane < deg) {
            unsigned long long e = __ldg(&g_edge[beg + base + lane]);
            lo = (unsigned)e;
            hi = (unsigned)(e >> 32);
        }
#pragma unroll 4
        for (int j = 0; j < n; j++) {
            int s = (int)__shfl_sync(~0u, lo, j);
            float w = __uint_as_float(__shfl_sync(~0u, hi, j));
            uint2 vr = __ldg((const uint2*)(h + (size_t)s * FDIM) + lane);
            float2 v01 = __half22float2(*(__half2*)&vr.x);
            float2 v23 = __half22float2(*(__half2*)&vr.y);
            acc.x += w * v01.x; acc.y += w * v01.y;
            acc.z += w * v23.x; acc.w += w * v23.y;
        }
    }
    return acc;
}

// conv-1/2 flavor: relu + fp16 store for the next GEMM
__global__ void agg_relu16(const __half* __restrict__ h, const float* __restrict__ bias,
                           __half* __restrict__ out16) {
    int warpid = (blockIdx.x * blockDim.x + threadIdx.x) >> 5;
    int lane = threadIdx.x & 31;
    if (warpid >= N_NODES) return;
    float4 a = agg_row(h, bias, warpid, lane);
    a.x = fmaxf(a.x, 0.f); a.y = fmaxf(a.y, 0.f);
    a.z = fmaxf(a.z, 0.f); a.w = fmaxf(a.w, 0.f);
    __half2 p0 = __floats2half2_rn(a.x, a.y);
    __half2 p1 = __floats2half2_rn(a.z, a.w);
    *(uint2*)(out16 + (size_t)warpid * FDIM + lane * 4) =
        make_uint2(*(uint32_t*)&p0, *(uint32_t*)&p1);
}

// conv-3 flavor: fp32 for pooling
__global__ void agg_f32(const __half* __restrict__ h, const float* __restrict__ bias,
                        float* __restrict__ out) {
    int warpid = (blockIdx.x * blockDim.x + threadIdx.x) >> 5;
    int lane = threadIdx.x & 31;
    if (warpid >= N_NODES) return;
    float4 a = agg_row(h, bias, warpid, lane);
    ((float4*)(out + (size_t)warpid * FDIM))[lane] = a;
}

// ---------------- pooling ----------------------------------------------------
__global__ void pool_kernel(const int* __restrict__ batch) {
    int warpid = (blockIdx.x * blockDim.x + threadIdx.x) >> 5;
    int lane = threadIdx.x & 31;
    int beg = warpid * 32;
    if (beg >= N_NODES) return;
    int end = min(beg + 32, N_NODES);

    int cur = batch[beg];
    float4 s = make_float4(0.f, 0.f, 0.f, 0.f);
    float4 m = make_float4(-INFINITY, -INFINITY, -INFINITY, -INFINITY);
    int cnt = 0;

    for (int node = beg; node < end; node++) {
        int b = batch[node];
        if (b != cur) {
            int base = cur * FDIM + lane * 4;
            atomicAdd(&g_sums[base + 0], s.x); atomicAdd(&g_sums[base + 1], s.y);
            atomicAdd(&g_sums[base + 2], s.z); atomicAdd(&g_sums[base + 3], s.w);
            atomicMax(&g_maxenc[base + 0], enc_max(m.x));
            atomicMax(&g_maxenc[base + 1], enc_max(m.y));
            atomicMax(&g_maxenc[base + 2], enc_max(m.z));
            atomicMax(&g_maxenc[base + 3], enc_max(m.w));
            if (lane == 0) atomicAdd(&g_cnt[cur], cnt);
            s = make_float4(0.f, 0.f, 0.f, 0.f);
            m = make_float4(-INFINITY, -INFINITY, -INFINITY, -INFINITY);
            cnt = 0;
            cur = b;
        }
        float4 v = ((const float4*)(g_agg + (size_t)node * FDIM))[lane];
        s.x += v.x; s.y += v.y; s.z += v.z; s.w += v.w;
        m.x = fmaxf(m.x, v.x); m.y = fmaxf(m.y, v.y);
        m.z = fmaxf(m.z, v.z); m.w = fmaxf(m.w, v.w);
        cnt++;
    }
    int base = cur * FDIM + lane * 4;
    atomicAdd(&g_sums[base + 0], s.x); atomicAdd(&g_sums[base + 1], s.y);
    atomicAdd(&g_sums[base + 2], s.z); atomicAdd(&g_sums[base + 3], s.w);
    atomicMax(&g_maxenc[base + 0], enc_max(m.x));
    atomicMax(&g_maxenc[base + 1], enc_max(m.y));
    atomicMax(&g_maxenc[base + 2], enc_max(m.z));
    atomicMax(&g_maxenc[base + 3], enc_max(m.w));
    if (lane == 0) atomicAdd(&g_cnt[cur], cnt);
}

// ---------------- classifier head -------------------------------------------
__global__ void classifier_kernel(const float* __restrict__ Wc1, const float* __restrict__ bc1,
                                  const float* __restrict__ Wc2, const float* __restrict__ bc2,
                                  float* __restrict__ out) {
    int g = blockIdx.x, t = threadIdx.x;
    __shared__ float gv[256];
    __shared__ float hs[128];

    int cnt = g_cnt[g];
    float inv = 1.0f / (float)max(cnt, 1);
    gv[t] = g_sums[g * FDIM + t] * inv;
    unsigned e = g_maxenc[g * FDIM + t];
    gv[128 + t] = (cnt == 0) ? 0.0f : dec_max(e);
    __syncthreads();

    float acc = bc1[t];
#pragma unroll 8
    for (int k = 0; k < 256; k++) acc += gv[k] * Wc1[k * 128 + t];
    hs[t] = fmaxf(acc, 0.0f);
    __syncthreads();

    if (t < 10) {
        float o = bc2[t];
#pragma unroll 8
        for (int k = 0; k < 128; k++) o += hs[k] * Wc2[k * 10 + t];
        out[g * 10 + t] = o;
    }
}

// ---------------- launch -----------------------------------------------------
extern "C" void kernel_launch(void* const* d_in, const int* in_sizes, int n_in,
                              void* d_out, int out_size) {
    const float* x     = (const float*)d_in[0];
    const int*   ei    = (const int*)d_in[1];
    const int*   src   = ei;
    const int*   dst   = ei + N_EDGES;
    const int*   batch = (const int*)d_in[2];
    const float* W1 = (const float*)d_in[3];  const float* b1 = (const float*)d_in[4];
    const float* W2 = (const float*)d_in[5];  const float* b2 = (const float*)d_in[6];
    const float* W3 = (const float*)d_in[7];  const float* b3 = (const float*)d_in[8];
    const float* Wc1 = (const float*)d_in[9]; const float* bc1 = (const float*)d_in[10];
    const float* Wc2 = (const float*)d_in[11]; const float* bc2 = (const float*)d_in[12];
    float* out = (float*)d_out;

    static cudaStream_t s2 = nullptr;
    static cudaEvent_t ev_fork = nullptr, ev_join = nullptr;
    if (s2 == nullptr) {
        cudaStreamCreateWithFlags(&s2, cudaStreamNonBlocking);
        cudaEventCreateWithFlags(&ev_fork, cudaEventDisableTiming);
        cudaEventCreateWithFlags(&ev_join, cudaEventDisableTiming);
        cudaFuncSetAttribute(gemm_f16, cudaFuncAttributeMaxDynamicSharedMemorySize,
                             SMEM_G);
    }

    float* ag; cudaGetSymbolAddress((void**)&ag, g_agg);
    __half* a16; cudaGetSymbolAddress((void**)&a16, g_a16);
    __half* h16; cudaGetSymbolAddress((void**)&h16, g_h16);
    __half* wh; cudaGetSymbolAddress((void**)&wh, g_wh);
    __half* wl; cudaGetSymbolAddress((void**)&wl, g_wl);

    const int GEMM_BLOCKS = (N_NODES + 127) / 128;          // 782
    const int AGG_BLOCKS  = (N_NODES * 32 + 255) / 256;     // 12500

    // fork: preprocessing on s2 concurrent with splits + G1 on main
    cudaEventRecord(ev_fork, 0);
    cudaStreamWaitEvent(s2, ev_fork, 0);

    zero_kernel<<<(N_NODES + 255) / 256, 256, 0, s2>>>();
    hist_kernel<<<2048, 256, 0, s2>>>(dst);
    scan_part<<<SCAN_BLOCKS, 256, 0, s2>>>();
    scan_mid<<<1, 256, 0, s2>>>();
    scan_final<<<SCAN_BLOCKS, 256, 0, s2>>>();
    scatter_kernel<<<2048, 256, 0, s2>>>(src, dst);
    cudaEventRecord(ev_join, s2);

    split_w<<<(3 * FDIM * FDIM + 255) / 256, 256>>>(W1, W2, W3);
    split_x<<<(N_NODES * FDIM / 4 + 255) / 256, 256>>>(x);
    gemm_f16<<<GEMM_BLOCKS, 256, SMEM_G>>>(a16, wh, wl, h16);               // G1

    cudaStreamWaitEvent(0, ev_join, 0);                     // A1 needs CSR

    agg_relu16<<<AGG_BLOCKS, 256>>>(h16, b1, a16);          // A1 -> fp16
    gemm_f16<<<GEMM_BLOCKS, 256, SMEM_G>>>(a16, wh + FDIM * FDIM,
                                           wl + FDIM * FDIM, h16);          // G2
    agg_relu16<<<AGG_BLOCKS, 256>>>(h16, b2, a16);          // A2 -> fp16
    gemm_f16<<<GEMM_BLOCKS, 256, SMEM_G>>>(a16, wh + 2 * FDIM * FDIM,
                                           wl + 2 * FDIM * FDIM, h16);      // G3
    agg_f32<<<AGG_BLOCKS, 256>>>(h16, b3, ag);              // A3 -> fp32

    int pool_warps = (N_NODES + 31) / 32;
    pool_kernel<<<(pool_warps * 32 + 255) / 256, 256>>>(batch);
    classifier_kernel<<<N_GRAPHS, 128>>>(Wc1, bc1, Wc2, bc2, out);
}